// round 16
// baseline (speedup 1.0000x reference)
#include <cuda_runtime.h>

// Model_69080253989304 — 1-layer tanh RNN, SEQ=4096, BATCH=8192, HID=4.
// R13: R12 (4 lanes/chain, one warp-wide tanh per step; 139us) with:
//  (1) balanced FMA consume tree: after the last SHFL arrives only fma+add
//      remain (8 cyc) instead of a 3-deep linear chain (12 cyc);
//  (2) no shared memory: 16-deep per-thread REGISTER prefetch of x (1 float
//      per step per thread at 4 lanes/chain) -> no cp.async/STS/LDS and no
//      per-chunk __syncthreads; warps fully decoupled;
//  (3) shfl issue order = consumption order (ha, hb, hc).
// Chain ~= tanh_lat + shfl(26) + fma+add(8) ~= 54 cyc/step.
// 128 CTAs x 256 thr = 2 warps/SMSP on 128 SMs; x loads coalesced (addr=base+tid).

#define SEQ    4096
#define BATCH  8192
#define PF     16            // register prefetch depth (steps)

__device__ __forceinline__ float tanh_fast(float x) {
    float r;
    asm("tanh.approx.f32 %0, %1;" : "=f"(r) : "f"(x));
    return r;
}

__global__ void __launch_bounds__(256, 1) rnn_scan_kernel(
    const float* __restrict__ x,      // (SEQ, BATCH, 1)
    const float* __restrict__ h0,     // (1, BATCH, HID)
    const float* __restrict__ W_ih,   // (HID, 1)
    const float* __restrict__ b_ih,   // (HID,)
    const float* __restrict__ W_hh,   // (HID, HID) row-major
    const float* __restrict__ b_hh,   // (HID,)
    const float* __restrict__ fc_W,   // (1, HID)
    const float* __restrict__ fc_b,   // (1,)
    float* __restrict__ out)          // [BATCH] y_last ++ [BATCH*HID] hn
{
    const int tid  = threadIdx.x;
    const int comp = tid & 3;             // h component owned by this lane
    const int cl   = tid >> 2;            // chain-local index 0..63
    const int b    = blockIdx.x * 64 + cl;

    // per-lane weight row of W_hh, ordered by shfl partner (bfly 1,2,3)
    const int r = comp * 4;
    const float wo = W_hh[r + comp];
    const float wa = W_hh[r + (comp ^ 1)];
    const float wb = W_hh[r + (comp ^ 2)];
    const float wc = W_hh[r + (comp ^ 3)];
    const float wi = W_ih[comp];
    const float cb = b_ih[comp] + b_hh[comp];

    // h0 / x column for this lane. x address per step = step*BATCH + b
    // (each float read by its 4-lane quad via broadcast; 64B/warp/step).
    const float* xp = x + b;
    float h = h0[(size_t)blockIdx.x * 256 + tid];   // coalesced (=b*4+comp)

    // ---- register prefetch pipeline: PF steps ahead ----
    float xs[PF];
#pragma unroll
    for (int i = 0; i < PF; ++i) xs[i] = xp[(size_t)i * BATCH];

    for (int t0 = 0; t0 < SEQ; t0 += PF) {
        // clamped prefetch base: last block reloads block 0 (values unused)
        const float* pn = xp + (size_t)((t0 + PF < SEQ) ? (t0 + PF) : 0) * BATCH;

#pragma unroll
        for (int i = 0; i < PF; ++i) {
            const float xv = xs[i];
            xs[i] = pn[(size_t)i * BATCH];          // refill slot (off-chain)
            const float cc = fmaf(wi, xv, cb);      // off the critical chain

            // exchange h within the quad; issue in consumption order
            const float ha = __shfl_xor_sync(0xffffffffu, h, 1);
            const float hb = __shfl_xor_sync(0xffffffffu, h, 2);
            const float hc = __shfl_xor_sync(0xffffffffu, h, 3);

            // balanced consume tree: depth after last shfl = fma + add
            const float t1 = fmaf(wa, ha, fmaf(wo, h, cc));
            const float t2 = fmaf(wc, hc, wb * hb);
            h = tanh_fast(t1 + t2);                 // ONE MUFU instr / step
        }
    }

    // ---- epilogue: y = fc(h_T) via quad reduction; hn coalesced write ----
    float p = fc_W[comp] * h;
    p += __shfl_xor_sync(0xffffffffu, p, 1);
    p += __shfl_xor_sync(0xffffffffu, p, 2);
    if (comp == 0) out[b] = p + fc_b[0];                       // y_last
    out[(size_t)BATCH + (size_t)blockIdx.x * 256 + tid] = h;   // hn

}

extern "C" void kernel_launch(void* const* d_in, const int* in_sizes, int n_in,
                              void* d_out, int out_size) {
    const float* x    = (const float*)d_in[0];
    const float* h0   = (const float*)d_in[1];
    const float* W_ih = (const float*)d_in[2];
    const float* b_ih = (const float*)d_in[3];
    const float* W_hh = (const float*)d_in[4];
    const float* b_hh = (const float*)d_in[5];
    const float* fc_W = (const float*)d_in[6];
    const float* fc_b = (const float*)d_in[7];
    float* out = (float*)d_out;

    rnn_scan_kernel<<<(BATCH * 4) / 256, 256>>>(x, h0, W_ih, b_ih, W_hh, b_hh,
                                                fc_W, fc_b, out);
}

// round 17
// speedup vs baseline: 1.6198x; 1.6198x over previous
#include <cuda_runtime.h>

// Model_69080253989304 — 1-layer tanh RNN, SEQ=4096, BATCH=8192, HID=4.
// R16 = R12 (best structure: smem + cp.async staging, 139us) + the two
// chain-shortening tweaks from R13 that were NOT implicated in its regression:
//  (1) balanced FMA consume tree (depth after last SHFL = fma+add, 8 cyc,
//      instead of 3 dependent FMAs = 12 cyc);
//  (2) shfl issue order matches consumption order.
// R13's register LDG pipeline is reverted: 16 outstanding LDGs oversubscribe
// the 6 scoreboard slots and expose DRAM latency on the serial chain
// (139 -> 240us). cp.async wait_group semantics avoid that entirely.
// 4 lanes per chain; one warp-wide MUFU.TANH per step.
// 128 CTAs x 256 thr = 2 warps/SMSP on 128 SMs.

#define SEQ    4096
#define BATCH  8192
#define CHUNK  32
#define NCHUNK (SEQ / CHUNK)
#define CPC    64            // chains per CTA

__device__ __forceinline__ float tanh_fast(float x) {
    float r;
    asm("tanh.approx.f32 %0, %1;" : "=f"(r) : "f"(x));
    return r;
}

__global__ void __launch_bounds__(256, 1) rnn_scan_kernel(
    const float* __restrict__ x,      // (SEQ, BATCH, 1)
    const float* __restrict__ h0,     // (1, BATCH, HID)
    const float* __restrict__ W_ih,   // (HID, 1)
    const float* __restrict__ b_ih,   // (HID,)
    const float* __restrict__ W_hh,   // (HID, HID) row-major
    const float* __restrict__ b_hh,   // (HID,)
    const float* __restrict__ fc_W,   // (1, HID)
    const float* __restrict__ fc_b,   // (1,)
    float* __restrict__ out)          // [BATCH] y_last ++ [BATCH*HID] hn
{
    __shared__ float xb[2][CHUNK][CPC];   // 16 KB

    const int tid  = threadIdx.x;
    const int comp = tid & 3;             // h component owned by this lane
    const int cl   = tid >> 2;            // chain-local index 0..63
    const int b    = blockIdx.x * CPC + cl;

    // per-lane weight row of W_hh, ordered by shfl partner (bfly 1,2,3)
    const int r = comp * 4;
    const float wo = W_hh[r + comp];
    const float wa = W_hh[r + (comp ^ 1)];
    const float wb = W_hh[r + (comp ^ 2)];
    const float wc = W_hh[r + (comp ^ 3)];
    const float wi = W_ih[comp];
    const float cb = b_ih[comp] + b_hh[comp];

    float h = h0[(size_t)blockIdx.x * 256 + tid];   // coalesced (=b*4+comp)

    const size_t gbase = (size_t)blockIdx.x * CPC;

    // ---- prologue: prefetch chunk 0 into buffer 0 (8 elems per thread) ----
#pragma unroll
    for (int k = 0; k < 8; ++k) {
        const int idx = k * 256 + tid;
        const int i   = idx >> 6;
        const int c   = idx & 63;
        unsigned dst = (unsigned)__cvta_generic_to_shared(&xb[0][i][c]);
        asm volatile("cp.async.ca.shared.global [%0], [%1], 4;"
                     :: "r"(dst), "l"(x + (size_t)i * BATCH + gbase + c)
                     : "memory");
    }
    asm volatile("cp.async.commit_group;" ::: "memory");

    for (int n = 0; n < NCHUNK; ++n) {
        asm volatile("cp.async.wait_group 0;" ::: "memory");
        __syncthreads();   // publish chunk n to all warps; fences prev reads

        const int cur  = n & 1;
        const int nrow = (n + 1 < NCHUNK) ? (n + 1) * CHUNK : 0;
        // issue prefetch of chunk n+1 before compute so it overlaps
#pragma unroll
        for (int k = 0; k < 8; ++k) {
            const int idx = k * 256 + tid;
            const int i   = idx >> 6;
            const int c   = idx & 63;
            unsigned dst = (unsigned)__cvta_generic_to_shared(&xb[cur ^ 1][i][c]);
            asm volatile("cp.async.ca.shared.global [%0], [%1], 4;"
                         :: "r"(dst), "l"(x + (size_t)(nrow + i) * BATCH + gbase + c)
                         : "memory");
        }
        asm volatile("cp.async.commit_group;" ::: "memory");

#pragma unroll
        for (int i = 0; i < CHUNK; ++i) {
            const float xv = xb[cur][i][cl];          // quad-broadcast LDS
            const float cc = fmaf(wi, xv, cb);        // off the critical chain

            // exchange h within the quad; issue in consumption order
            const float ha = __shfl_xor_sync(0xffffffffu, h, 1);
            const float hb = __shfl_xor_sync(0xffffffffu, h, 2);
            const float hc = __shfl_xor_sync(0xffffffffu, h, 3);

            // balanced consume tree: depth after last shfl = fma + add
            const float t1 = fmaf(wa, ha, fmaf(wo, h, cc));
            const float t2 = fmaf(wc, hc, wb * hb);
            h = tanh_fast(t1 + t2);                   // ONE MUFU instr / step
        }
    }

    // ---- epilogue: y = fc(h_T) via quad reduction; hn coalesced write ----
    float p = fc_W[comp] * h;
    p += __shfl_xor_sync(0xffffffffu, p, 1);
    p += __shfl_xor_sync(0xffffffffu, p, 2);
    if (comp == 0) out[b] = p + fc_b[0];                       // y_last
    out[(size_t)BATCH + (size_t)blockIdx.x * 256 + tid] = h;   // hn
}

extern "C" void kernel_launch(void* const* d_in, const int* in_sizes, int n_in,
                              void* d_out, int out_size) {
    const float* x    = (const float*)d_in[0];
    const float* h0   = (const float*)d_in[1];
    const float* W_ih = (const float*)d_in[2];
    const float* b_ih = (const float*)d_in[3];
    const float* W_hh = (const float*)d_in[4];
    const float* b_hh = (const float*)d_in[5];
    const float* fc_W = (const float*)d_in[6];
    const float* fc_b = (const float*)d_in[7];
    float* out = (float*)d_out;

    rnn_scan_kernel<<<(BATCH * 4) / 256, 256>>>(x, h0, W_ih, b_ih, W_hh, b_hh,
                                                fc_W, fc_b, out);
}